// round 4
// baseline (speedup 1.0000x reference)
#include <cuda_runtime.h>
#include <cstdint>

#define HID   1024
#define BATCH 64
#define SEQ   512
#define G3    3072
#define BT    (BATCH * SEQ)
#define DIN0  118

#define NBLK  128          // persistent blocks (all co-resident; <= 148 SMs)
#define NCOL  24           // G3 / NBLK  (N-slice of Whh per block)
#define KC    128          // k-chunk staged in smem
#define NTHR  128

// ---------------- scratch (device globals; no allocation allowed) ----------
__device__ float g_xg[(size_t)BT * G3];        // input projections for current layer
__device__ float g_yA[(size_t)BT * HID];       // layer outputs ping
__device__ float g_yB[(size_t)BT * HID];       // layer outputs pong
__device__ float g_hg[BATCH * G3];             // h @ Whh^T for current step
__device__ float g_hT[HID * BATCH];            // transposed hidden  hT[k][b]
__device__ float g_hb[BATCH * HID];            // hidden, batch-major h[b][k]
__device__ unsigned long long g_bar_count;     // monotonic barrier arrivals
__device__ unsigned long long g_bar_epoch;     // monotonic barrier epoch

// ---------------------------------------------------------------------------
// software grid barrier (all NBLK blocks resident). Epochs are absolute and
// monotonic across launches/replays (64-bit: no overflow).
// ---------------------------------------------------------------------------
__device__ __forceinline__ void grid_barrier(unsigned long long ep) {
    __threadfence();          // make this thread's prior writes visible
    __syncthreads();          // all threads of block fenced & arrived
    if (threadIdx.x == 0) {
        unsigned long long total = atomicAdd(&g_bar_count, 1ull) + 1ull;
        if (total == ep * (unsigned long long)NBLK) {
            atomicExch(&g_bar_epoch, ep);     // release
        } else {
            while (*(volatile unsigned long long*)&g_bar_epoch < ep)
                __nanosleep(64);
        }
    }
    __syncthreads();
    __threadfence();
}

__device__ __forceinline__ float fsigmoid(float x) {
    return 1.f / (1.f + __expf(-x));
}
__device__ __forceinline__ float ftanh(float x) {
    // 2*sigmoid(2x)-1 : saturates cleanly (no inf/inf)
    return 2.f / (1.f + __expf(-2.f * x)) - 1.f;
}

// ---------------------------------------------------------------------------
// cp.async helpers
// ---------------------------------------------------------------------------
__device__ __forceinline__ void cp_async16(uint32_t smem_dst, const void* gptr) {
    asm volatile("cp.async.cg.shared.global [%0], [%1], 16;\n"
                 :: "r"(smem_dst), "l"(gptr));
}
__device__ __forceinline__ void cp_commit() {
    asm volatile("cp.async.commit_group;\n");
}
__device__ __forceinline__ void cp_wait1() {
    asm volatile("cp.async.wait_group 1;\n");
}

// ---------------------------------------------------------------------------
// Persistent per-layer GRU kernel.
//   smem: W_s[1024][24] (Whh slice, resident all steps)  96 KB
//         h_s[2][KC][64] (double-buffered hT chunks)      64 KB
// Per step:  (t>0) hg[b][n0..n0+23] = sum_k h[b][k]*Whh[n][k]   (FMA-bound)
//            barrier ; fused gates (4b x 128n tile per block) ; barrier
// ---------------------------------------------------------------------------
__global__ __launch_bounds__(NTHR, 1) void gru_layer_kernel(
    const float* __restrict__ Whh, const float* __restrict__ bhh, int ysel)
{
    extern __shared__ float sm[];
    float* W_s = sm;                      // HID*NCOL floats (k-major: W_s[k][j])
    float* h_s = sm + HID * NCOL;         // 2*KC*BATCH floats

    const int tid = threadIdx.x;
    const int bid = blockIdx.x;
    const int n0  = bid * NCOL;
    const int tn  = tid & 7;              // 8 n-groups of 3
    const int tm  = tid >> 3;             // 16 m-groups of 4

    // ---- load Whh slice into smem (once) ----
    for (int idx = tid; idx < NCOL * HID; idx += NTHR) {
        int j = idx >> 10;                // 0..23
        int k = idx & (HID - 1);
        W_s[k * NCOL + j] = Whh[(size_t)(n0 + j) * HID + k];
    }

    unsigned long long ep = *(volatile unsigned long long*)&g_bar_epoch;

    // gate-phase partition: block -> (4 batches) x (128 hidden cols)
    const int nb = bid & 7;
    const int bb = bid >> 3;
    const int gn = nb * 128 + tid;

    const uint32_t s_h = (uint32_t)__cvta_generic_to_shared(h_s);

    for (int t = 0; t < SEQ; t++) {
        if (t > 0) {
            float acc[4][3];
#pragma unroll
            for (int i = 0; i < 4; i++)
#pragma unroll
                for (int j = 0; j < 3; j++) acc[i][j] = 0.f;

            // prologue: stage chunks 0 and 1
#pragma unroll
            for (int c = 0; c < 2; c++) {
                uint32_t dst = s_h + (uint32_t)(c & 1) * (KC * BATCH * 4);
                const float* src = g_hT + (size_t)c * KC * BATCH;
#pragma unroll
                for (int j = 0; j < (KC * BATCH) / (NTHR * 4); j++) {
                    int idx4 = tid + j * NTHR;
                    cp_async16(dst + (uint32_t)idx4 * 16, src + (size_t)idx4 * 4);
                }
                cp_commit();
            }

            for (int c = 0; c < HID / KC; c++) {
                cp_wait1();                 // chunk c landed
                __syncthreads();
                const float* hb = h_s + (c & 1) * (KC * BATCH);
                const float* Wc = W_s + (size_t)c * KC * NCOL;   // <-- chunk offset (bug fix)
#pragma unroll 4
                for (int k = 0; k < KC; k++) {
                    float4 a = *(const float4*)&hb[k * BATCH + tm * 4];
                    float w0 = Wc[k * NCOL + tn * 3 + 0];
                    float w1 = Wc[k * NCOL + tn * 3 + 1];
                    float w2 = Wc[k * NCOL + tn * 3 + 2];
                    acc[0][0] = fmaf(a.x, w0, acc[0][0]);
                    acc[0][1] = fmaf(a.x, w1, acc[0][1]);
                    acc[0][2] = fmaf(a.x, w2, acc[0][2]);
                    acc[1][0] = fmaf(a.y, w0, acc[1][0]);
                    acc[1][1] = fmaf(a.y, w1, acc[1][1]);
                    acc[1][2] = fmaf(a.y, w2, acc[1][2]);
                    acc[2][0] = fmaf(a.z, w0, acc[2][0]);
                    acc[2][1] = fmaf(a.z, w1, acc[2][1]);
                    acc[2][2] = fmaf(a.z, w2, acc[2][2]);
                    acc[3][0] = fmaf(a.w, w0, acc[3][0]);
                    acc[3][1] = fmaf(a.w, w1, acc[3][1]);
                    acc[3][2] = fmaf(a.w, w2, acc[3][2]);
                }
                __syncthreads();            // done reading buf (c&1)
                if (c + 2 < HID / KC) {     // stage chunk c+2 into buf (c&1)
                    uint32_t dst = s_h + (uint32_t)(c & 1) * (KC * BATCH * 4);
                    const float* src = g_hT + (size_t)(c + 2) * KC * BATCH;
#pragma unroll
                    for (int j = 0; j < (KC * BATCH) / (NTHR * 4); j++) {
                        int idx4 = tid + j * NTHR;
                        cp_async16(dst + (uint32_t)idx4 * 16, src + (size_t)idx4 * 4);
                    }
                }
                cp_commit();                // (possibly empty) keeps wait_group math uniform
            }

            // write hg slice
#pragma unroll
            for (int i = 0; i < 4; i++) {
                int b = tm * 4 + i;
#pragma unroll
                for (int j = 0; j < 3; j++)
                    g_hg[(size_t)b * G3 + n0 + tn * 3 + j] = acc[i][j];
            }
        }

        grid_barrier(++ep);

        // ---- fused gate phase: 4 batches x 1 column per thread ----
#pragma unroll
        for (int e = 0; e < 4; e++) {
            int b = bb * 4 + e;
            size_t bt = (size_t)b * SEQ + t;
            const float* xgrow = g_xg + bt * G3;
            float vxr = xgrow[gn];
            float vxz = xgrow[HID + gn];
            float vxn = xgrow[2 * HID + gn];

            float hr = bhh[gn];
            float hz = bhh[HID + gn];
            float hn = bhh[2 * HID + gn];
            float hp = 0.f;
            if (t > 0) {
                hr += __ldcg(&g_hg[(size_t)b * G3 + gn]);
                hz += __ldcg(&g_hg[(size_t)b * G3 + HID + gn]);
                hn += __ldcg(&g_hg[(size_t)b * G3 + 2 * HID + gn]);
                hp = g_hb[b * HID + gn];          // own tile (same thread wrote it)
            }
            float r  = fsigmoid(vxr + hr);
            float z  = fsigmoid(vxz + hz);
            float nn = ftanh(vxn + r * hn);
            float h  = (1.f - z) * nn + z * hp;

            g_hb[b * HID + gn]   = h;             // batch-major (gate reuse)
            g_hT[gn * BATCH + b] = h;             // transposed (GEMM staging)
            if (ysel == 1)      g_yA[bt * HID + gn] = h;
            else if (ysel == 2) g_yB[bt * HID + gn] = h;
        }

        grid_barrier(++ep);
    }
}

// ---------------------------------------------------------------------------
// Batched input projection: g_xg[m, n] = sum_k A[m,k] * W[n,k] + bias[n]
// 128x128x8 SGEMM, 8x8 register tiles, 256 threads.
// ---------------------------------------------------------------------------
__global__ __launch_bounds__(256) void gemm_xg_kernel(
    const float* __restrict__ x_in, int a_sel, int K,
    const float* __restrict__ W, const float* __restrict__ bias)
{
    const float* A = (a_sel == 0) ? x_in : (a_sel == 1 ? g_yA : g_yB);

    __shared__ float As[8][128];
    __shared__ float Bs[8][128];

    const int n0 = blockIdx.x * 128;
    const int m0 = blockIdx.y * 128;
    const int tid = threadIdx.x;
    const int tx = tid & 15;
    const int ty = tid >> 4;

    float acc[8][8];
#pragma unroll
    for (int i = 0; i < 8; i++)
#pragma unroll
        for (int j = 0; j < 8; j++) acc[i][j] = 0.f;

    const int nkt = (K + 7) >> 3;
    for (int kt = 0; kt < nkt; kt++) {
        const int k0 = kt << 3;
#pragma unroll
        for (int i = 0; i < 4; i++) {
            int ii = tid + i * 256;
            int m = ii >> 3, k = ii & 7;
            As[k][m] = (k0 + k < K) ? A[(size_t)(m0 + m) * K + (k0 + k)] : 0.f;
        }
#pragma unroll
        for (int i = 0; i < 4; i++) {
            int ii = tid + i * 256;
            int n = ii >> 3, k = ii & 7;
            Bs[k][n] = (k0 + k < K) ? W[(size_t)(n0 + n) * K + (k0 + k)] : 0.f;
        }
        __syncthreads();
#pragma unroll
        for (int k = 0; k < 8; k++) {
            float a[8], b[8];
#pragma unroll
            for (int i = 0; i < 8; i++) a[i] = As[k][ty * 8 + i];
#pragma unroll
            for (int j = 0; j < 8; j++) b[j] = Bs[k][tx * 8 + j];
#pragma unroll
            for (int i = 0; i < 8; i++)
#pragma unroll
                for (int j = 0; j < 8; j++)
                    acc[i][j] = fmaf(a[i], b[j], acc[i][j]);
        }
        __syncthreads();
    }

#pragma unroll
    for (int i = 0; i < 8; i++) {
        size_t row = (size_t)(m0 + ty * 8 + i) * G3;
#pragma unroll
        for (int j = 0; j < 8; j++) {
            int n = n0 + tx * 8 + j;
            g_xg[row + n] = acc[i][j] + bias[n];
        }
    }
}

// ---------------------------------------------------------------------------
// Final linear: out[b] = dot(h_last[b,:], W_lin) + b_lin
// ---------------------------------------------------------------------------
__global__ __launch_bounds__(256) void final_kernel(
    const float* __restrict__ Wlin, const float* __restrict__ blin,
    float* __restrict__ out)
{
    const int b = blockIdx.x;
    const float* h = g_hb + b * HID;
    float s = 0.f;
    for (int k = threadIdx.x; k < HID; k += 256) s += h[k] * Wlin[k];
#pragma unroll
    for (int o = 16; o > 0; o >>= 1) s += __shfl_down_sync(0xffffffffu, s, o);
    __shared__ float red[8];
    if ((threadIdx.x & 31) == 0) red[threadIdx.x >> 5] = s;
    __syncthreads();
    if (threadIdx.x < 8) {
        s = red[threadIdx.x];
#pragma unroll
        for (int o = 4; o > 0; o >>= 1) s += __shfl_down_sync(0xffu, s, o);
        if (threadIdx.x == 0) out[b] = s + blin[0];
    }
}

// ---------------------------------------------------------------------------
extern "C" void kernel_launch(void* const* d_in, const int* in_sizes, int n_in,
                              void* d_out, int out_size)
{
    const float* x      = (const float*)d_in[0];  // (64, 512, 118)
    const float* W_ih0  = (const float*)d_in[1];  // (3072, 118)
    const float* W_ih12 = (const float*)d_in[2];  // (2, 3072, 1024)
    const float* W_hh   = (const float*)d_in[3];  // (3, 3072, 1024)
    const float* b_ih   = (const float*)d_in[4];  // (3, 3072)
    const float* b_hh   = (const float*)d_in[5];  // (3, 3072)
    const float* W_lin  = (const float*)d_in[6];  // (1, 1024)
    const float* b_lin  = (const float*)d_in[7];  // (1,)
    float* out = (float*)d_out;                   // (64, 1)

    const int smem_bytes = (HID * NCOL + 2 * KC * BATCH) * sizeof(float); // 160 KB
    cudaFuncSetAttribute(gru_layer_kernel,
                         cudaFuncAttributeMaxDynamicSharedMemorySize, smem_bytes);

    for (int l = 0; l < 3; l++) {
        const float* Wih   = (l == 0) ? W_ih0 : (W_ih12 + (size_t)(l - 1) * G3 * HID);
        const int    K     = (l == 0) ? DIN0 : HID;
        const int    asel  = (l == 0) ? 0 : (l == 1 ? 1 : 2);
        const int    ysel  = (l == 0) ? 1 : (l == 1 ? 2 : 0);
        const float* Whh_l = W_hh + (size_t)l * G3 * HID;
        const float* bih_l = b_ih + (size_t)l * G3;
        const float* bhh_l = b_hh + (size_t)l * G3;

        dim3 ggrid(G3 / 128, BT / 128);
        gemm_xg_kernel<<<ggrid, 256>>>(x, asel, K, Wih, bih_l);

        gru_layer_kernel<<<NBLK, NTHR, smem_bytes>>>(Whh_l, bhh_l, ysel);
    }

    final_kernel<<<BATCH, 256>>>(W_lin, b_lin, out);
}

// round 5
// speedup vs baseline: 1.0927x; 1.0927x over previous
#include <cuda_runtime.h>
#include <cstdint>

#define HID   1024
#define BATCH 64
#define SEQ   512
#define G3    3072
#define BT    (BATCH * SEQ)
#define DIN0  118

#define NBLK  128          // persistent blocks (all co-resident; <= 148 SMs)
#define NCOLB 8            // HID columns per block (x3 gates = 24 Whh rows)
#define KC    128          // k-chunk staged in smem
#define NTHR  256

// ---------------- scratch (device globals; no allocation allowed) ----------
__device__ float g_xg[(size_t)BT * G3];        // input projections for current layer
__device__ float g_yA[(size_t)BT * HID];       // layer outputs ping
__device__ float g_yB[(size_t)BT * HID];       // layer outputs pong
__device__ float g_hT[HID * BATCH];            // transposed hidden  hT[k][b]
__device__ float g_hb[BATCH * HID];            // final hidden, batch-major
__device__ unsigned long long g_bar_count;     // monotonic barrier arrivals
__device__ unsigned long long g_bar_epoch;     // monotonic barrier epoch

// ---------------------------------------------------------------------------
// software grid barrier (all NBLK blocks resident). Epochs absolute/monotonic.
// ---------------------------------------------------------------------------
__device__ __forceinline__ void grid_barrier(unsigned long long ep) {
    __threadfence();
    __syncthreads();
    if (threadIdx.x == 0) {
        unsigned long long total = atomicAdd(&g_bar_count, 1ull) + 1ull;
        if (total == ep * (unsigned long long)NBLK) {
            atomicExch(&g_bar_epoch, ep);     // release
        } else {
            while (*(volatile unsigned long long*)&g_bar_epoch < ep)
                __nanosleep(64);
        }
    }
    __syncthreads();
    __threadfence();
}

__device__ __forceinline__ float fsigmoid(float x) {
    return 1.f / (1.f + __expf(-x));
}
__device__ __forceinline__ float ftanh(float x) {
    return 2.f / (1.f + __expf(-2.f * x)) - 1.f;
}

// ---------------------------------------------------------------------------
// cp.async helpers
// ---------------------------------------------------------------------------
__device__ __forceinline__ void cp_async16(uint32_t smem_dst, const void* gptr) {
    asm volatile("cp.async.cg.shared.global [%0], [%1], 16;\n"
                 :: "r"(smem_dst), "l"(gptr));
}
__device__ __forceinline__ void cp_commit() {
    asm volatile("cp.async.commit_group;\n");
}
__device__ __forceinline__ void cp_wait1() {
    asm volatile("cp.async.wait_group 1;\n");
}

// ---------------------------------------------------------------------------
// Persistent per-layer GRU kernel, gate-fused column partition.
// Block i owns HID-columns c0..c0+7 (c0 = 8*i) for ALL THREE gates:
//   Whh rows {g*HID + c0 + tn : g=0..2, tn=0..7}  -> smem W_s[k][24], j=tn*3+g
// Thread (tn = tid&7, tm = tid>>3) accumulates (hr,hz,hn) for col c=c0+tn and
// batches b = 2*tm, 2*tm+1, then applies the GRU gates IN REGISTER — no hg
// gmem round trip, h_prev kept in registers, ONE grid barrier per step.
//   smem: W_s[1024][24] (96 KB, resident) + h_s[2][KC][64] (64 KB, cp.async DB)
// ---------------------------------------------------------------------------
__global__ __launch_bounds__(NTHR, 1) void gru_layer_kernel(
    const float* __restrict__ Whh, const float* __restrict__ bhh, int ysel)
{
    extern __shared__ float sm[];
    float* W_s = sm;                      // HID*24 floats, k-major
    float* h_s = sm + HID * 24;           // 2*KC*BATCH floats

    const int tid = threadIdx.x;
    const int bid = blockIdx.x;
    const int c0  = bid * NCOLB;
    const int tn  = tid & 7;              // column within block slice
    const int tm  = tid >> 3;             // 32 m-groups of 2 batches
    const int c   = c0 + tn;              // absolute HID column
    const int b0  = tm * 2;

    // ---- load Whh slice into smem (once): W_s[k*24 + tn*3 + g] ----
    for (int idx = tid; idx < 24 * HID; idx += NTHR) {
        int j = idx >> 10;                // 0..23
        int k = idx & (HID - 1);
        int jt = j / 3, jg = j - jt * 3;  // col-group, gate
        W_s[k * 24 + j] = Whh[(size_t)(jg * HID + c0 + jt) * HID + k];
    }

    // per-thread constants
    const float bh0 = bhh[c];
    const float bh1 = bhh[HID + c];
    const float bh2 = bhh[2 * HID + c];

    float hprev0 = 0.f, hprev1 = 0.f;     // h_{t-1} for (b0, c), (b0+1, c)

    unsigned long long ep = *(volatile unsigned long long*)&g_bar_epoch;
    const uint32_t s_h = (uint32_t)__cvta_generic_to_shared(h_s);

    for (int t = 0; t < SEQ; t++) {
        // ---- prefetch xg for this step (lands during the ~13us GEMM) ----
        const size_t r0 = ((size_t)b0 * SEQ + t) * G3;
        const size_t r1 = ((size_t)(b0 + 1) * SEQ + t) * G3;
        float x00 = __ldcg(&g_xg[r0 + c]);
        float x01 = __ldcg(&g_xg[r0 + HID + c]);
        float x02 = __ldcg(&g_xg[r0 + 2 * HID + c]);
        float x10 = __ldcg(&g_xg[r1 + c]);
        float x11 = __ldcg(&g_xg[r1 + HID + c]);
        float x12 = __ldcg(&g_xg[r1 + 2 * HID + c]);

        float a00 = 0.f, a01 = 0.f, a02 = 0.f;   // batch b0:  r,z,n
        float a10 = 0.f, a11 = 0.f, a12 = 0.f;   // batch b0+1

        if (t > 0) {
            // prologue: stage chunks 0 and 1
#pragma unroll
            for (int ch = 0; ch < 2; ch++) {
                uint32_t dst = s_h + (uint32_t)(ch & 1) * (KC * BATCH * 4);
                const float* src = g_hT + (size_t)ch * KC * BATCH;
#pragma unroll
                for (int j = 0; j < (KC * BATCH) / (NTHR * 4); j++) {
                    int idx4 = tid + j * NTHR;
                    cp_async16(dst + (uint32_t)idx4 * 16, src + (size_t)idx4 * 4);
                }
                cp_commit();
            }

            for (int ch = 0; ch < HID / KC; ch++) {
                cp_wait1();
                __syncthreads();
                const float* hb = h_s + (ch & 1) * (KC * BATCH);
                const float* Wc = W_s + (size_t)ch * KC * 24;
#pragma unroll 8
                for (int k = 0; k < KC; k++) {
                    float2 a = *(const float2*)&hb[k * BATCH + b0];
                    float w0 = Wc[k * 24 + tn * 3 + 0];
                    float w1 = Wc[k * 24 + tn * 3 + 1];
                    float w2 = Wc[k * 24 + tn * 3 + 2];
                    a00 = fmaf(a.x, w0, a00);
                    a01 = fmaf(a.x, w1, a01);
                    a02 = fmaf(a.x, w2, a02);
                    a10 = fmaf(a.y, w0, a10);
                    a11 = fmaf(a.y, w1, a11);
                    a12 = fmaf(a.y, w2, a12);
                }
                __syncthreads();
                if (ch + 2 < HID / KC) {
                    uint32_t dst = s_h + (uint32_t)(ch & 1) * (KC * BATCH * 4);
                    const float* src = g_hT + (size_t)(ch + 2) * KC * BATCH;
#pragma unroll
                    for (int j = 0; j < (KC * BATCH) / (NTHR * 4); j++) {
                        int idx4 = tid + j * NTHR;
                        cp_async16(dst + (uint32_t)idx4 * 16, src + (size_t)idx4 * 4);
                    }
                }
                cp_commit();     // (possibly empty) keeps wait_group math uniform
            }
        }

        // ---- gates, fully in register ----
        {
            float r  = fsigmoid(x00 + a00 + bh0);
            float z  = fsigmoid(x01 + a01 + bh1);
            float nn = ftanh(x02 + fmaf(r, a02 + bh2, 0.f));
            hprev0 = (1.f - z) * nn + z * hprev0;

            float r1g = fsigmoid(x10 + a10 + bh0);
            float z1g = fsigmoid(x11 + a11 + bh1);
            float n1g = ftanh(x12 + fmaf(r1g, a12 + bh2, 0.f));
            hprev1 = (1.f - z1g) * n1g + z1g * hprev1;
        }

        // hand-off for next step's GEMM (transposed, float2-contiguous)
        *(float2*)&g_hT[(size_t)c * BATCH + b0] = make_float2(hprev0, hprev1);

        if (ysel == 1) {
            g_yA[((size_t)b0 * SEQ + t) * HID + c]       = hprev0;
            g_yA[((size_t)(b0 + 1) * SEQ + t) * HID + c] = hprev1;
        } else if (ysel == 2) {
            g_yB[((size_t)b0 * SEQ + t) * HID + c]       = hprev0;
            g_yB[((size_t)(b0 + 1) * SEQ + t) * HID + c] = hprev1;
        }
        if (t == SEQ - 1) {
            g_hb[(size_t)b0 * HID + c]       = hprev0;
            g_hb[(size_t)(b0 + 1) * HID + c] = hprev1;
        }

        grid_barrier(++ep);    // hT visible to everyone before next step
    }
}

// ---------------------------------------------------------------------------
// Batched input projection: g_xg[m, n] = sum_k A[m,k] * W[n,k] + bias[n]
// 128x128x8 SGEMM, 8x8 register tiles, 256 threads.
// ---------------------------------------------------------------------------
__global__ __launch_bounds__(256) void gemm_xg_kernel(
    const float* __restrict__ x_in, int a_sel, int K,
    const float* __restrict__ W, const float* __restrict__ bias)
{
    const float* A = (a_sel == 0) ? x_in : (a_sel == 1 ? g_yA : g_yB);

    __shared__ float As[8][128];
    __shared__ float Bs[8][128];

    const int n0 = blockIdx.x * 128;
    const int m0 = blockIdx.y * 128;
    const int tid = threadIdx.x;
    const int tx = tid & 15;
    const int ty = tid >> 4;

    float acc[8][8];
#pragma unroll
    for (int i = 0; i < 8; i++)
#pragma unroll
        for (int j = 0; j < 8; j++) acc[i][j] = 0.f;

    const int nkt = (K + 7) >> 3;
    for (int kt = 0; kt < nkt; kt++) {
        const int k0 = kt << 3;
#pragma unroll
        for (int i = 0; i < 4; i++) {
            int ii = tid + i * 256;
            int m = ii >> 3, k = ii & 7;
            As[k][m] = (k0 + k < K) ? A[(size_t)(m0 + m) * K + (k0 + k)] : 0.f;
        }
#pragma unroll
        for (int i = 0; i < 4; i++) {
            int ii = tid + i * 256;
            int n = ii >> 3, k = ii & 7;
            Bs[k][n] = (k0 + k < K) ? W[(size_t)(n0 + n) * K + (k0 + k)] : 0.f;
        }
        __syncthreads();
#pragma unroll
        for (int k = 0; k < 8; k++) {
            float a[8], b[8];
#pragma unroll
            for (int i = 0; i < 8; i++) a[i] = As[k][ty * 8 + i];
#pragma unroll
            for (int j = 0; j < 8; j++) b[j] = Bs[k][tx * 8 + j];
#pragma unroll
            for (int i = 0; i < 8; i++)
#pragma unroll
                for (int j = 0; j < 8; j++)
                    acc[i][j] = fmaf(a[i], b[j], acc[i][j]);
        }
        __syncthreads();
    }

#pragma unroll
    for (int i = 0; i < 8; i++) {
        size_t row = (size_t)(m0 + ty * 8 + i) * G3;
#pragma unroll
        for (int j = 0; j < 8; j++) {
            int n = n0 + tx * 8 + j;
            g_xg[row + n] = acc[i][j] + bias[n];
        }
    }
}

// ---------------------------------------------------------------------------
// Final linear: out[b] = dot(h_last[b,:], W_lin) + b_lin
// ---------------------------------------------------------------------------
__global__ __launch_bounds__(256) void final_kernel(
    const float* __restrict__ Wlin, const float* __restrict__ blin,
    float* __restrict__ out)
{
    const int b = blockIdx.x;
    const float* h = g_hb + b * HID;
    float s = 0.f;
    for (int k = threadIdx.x; k < HID; k += 256) s += h[k] * Wlin[k];
#pragma unroll
    for (int o = 16; o > 0; o >>= 1) s += __shfl_down_sync(0xffffffffu, s, o);
    __shared__ float red[8];
    if ((threadIdx.x & 31) == 0) red[threadIdx.x >> 5] = s;
    __syncthreads();
    if (threadIdx.x < 8) {
        s = red[threadIdx.x];
#pragma unroll
        for (int o = 4; o > 0; o >>= 1) s += __shfl_down_sync(0xffu, s, o);
        if (threadIdx.x == 0) out[b] = s + blin[0];
    }
}

// ---------------------------------------------------------------------------
extern "C" void kernel_launch(void* const* d_in, const int* in_sizes, int n_in,
                              void* d_out, int out_size)
{
    const float* x      = (const float*)d_in[0];  // (64, 512, 118)
    const float* W_ih0  = (const float*)d_in[1];  // (3072, 118)
    const float* W_ih12 = (const float*)d_in[2];  // (2, 3072, 1024)
    const float* W_hh   = (const float*)d_in[3];  // (3, 3072, 1024)
    const float* b_ih   = (const float*)d_in[4];  // (3, 3072)
    const float* b_hh   = (const float*)d_in[5];  // (3, 3072)
    const float* W_lin  = (const float*)d_in[6];  // (1, 1024)
    const float* b_lin  = (const float*)d_in[7];  // (1,)
    float* out = (float*)d_out;                   // (64, 1)

    const int smem_bytes = (HID * 24 + 2 * KC * BATCH) * sizeof(float); // 160 KB
    cudaFuncSetAttribute(gru_layer_kernel,
                         cudaFuncAttributeMaxDynamicSharedMemorySize, smem_bytes);

    for (int l = 0; l < 3; l++) {
        const float* Wih   = (l == 0) ? W_ih0 : (W_ih12 + (size_t)(l - 1) * G3 * HID);
        const int    K     = (l == 0) ? DIN0 : HID;
        const int    asel  = (l == 0) ? 0 : (l == 1 ? 1 : 2);
        const int    ysel  = (l == 0) ? 1 : (l == 1 ? 2 : 0);
        const float* Whh_l = W_hh + (size_t)l * G3 * HID;
        const float* bih_l = b_ih + (size_t)l * G3;
        const float* bhh_l = b_hh + (size_t)l * G3;

        dim3 ggrid(G3 / 128, BT / 128);
        gemm_xg_kernel<<<ggrid, 256>>>(x, asel, K, Wih, bih_l);

        gru_layer_kernel<<<NBLK, NTHR, smem_bytes>>>(Whh_l, bhh_l, ysel);
    }

    final_kernel<<<BATCH, 256>>>(W_lin, b_lin, out);
}

// round 6
// speedup vs baseline: 1.3188x; 1.2069x over previous
#include <cuda_runtime.h>
#include <cstdint>

#define HID   1024
#define BATCH 64
#define SEQ   512
#define G3    3072
#define BT    (BATCH * SEQ)
#define DIN0  118

#define NBLK  128          // persistent blocks (all co-resident; <= 148 SMs)
#define NCOLB 8            // HID columns per block (x3 gates = 24 Whh rows)
#define KC    128          // k-chunk staged in smem (recurrent kernel)
#define NTHR  256

// ---------------- scratch (device globals; no allocation allowed) ----------
__device__ float g_xg[(size_t)BT * G3];        // input projections for current layer
__device__ float g_yA[(size_t)BT * HID];       // layer outputs ping
__device__ float g_yB[(size_t)BT * HID];       // layer outputs pong
__device__ float g_hT[HID * BATCH];            // transposed hidden  hT[k][b]
__device__ float g_hb[BATCH * HID];            // final hidden, batch-major
__device__ unsigned long long g_bar_count;     // monotonic barrier arrivals
__device__ unsigned long long g_bar_epoch;     // monotonic barrier epoch

// ---------------------------------------------------------------------------
// software grid barrier (all NBLK blocks resident). Epochs absolute/monotonic.
// ---------------------------------------------------------------------------
__device__ __forceinline__ void grid_barrier(unsigned long long ep) {
    __threadfence();
    __syncthreads();
    if (threadIdx.x == 0) {
        unsigned long long total = atomicAdd(&g_bar_count, 1ull) + 1ull;
        if (total == ep * (unsigned long long)NBLK) {
            atomicExch(&g_bar_epoch, ep);     // release
        } else {
            while (*(volatile unsigned long long*)&g_bar_epoch < ep)
                __nanosleep(64);
        }
    }
    __syncthreads();
    __threadfence();
}

__device__ __forceinline__ float fsigmoid(float x) {
    return 1.f / (1.f + __expf(-x));
}
__device__ __forceinline__ float ftanh(float x) {
    return 2.f / (1.f + __expf(-2.f * x)) - 1.f;
}

// ---------------------------------------------------------------------------
// cp.async helpers
// ---------------------------------------------------------------------------
__device__ __forceinline__ void cp_async16(uint32_t smem_dst, const void* gptr) {
    asm volatile("cp.async.cg.shared.global [%0], [%1], 16;\n"
                 :: "r"(smem_dst), "l"(gptr));
}
__device__ __forceinline__ void cp_commit() {
    asm volatile("cp.async.commit_group;\n");
}
__device__ __forceinline__ void cp_wait1() {
    asm volatile("cp.async.wait_group 1;\n");
}

// tf32 helpers
__device__ __forceinline__ uint32_t f2tf32(float x) {
    uint32_t r;
    asm("cvt.rna.tf32.f32 %0, %1;" : "=r"(r) : "f"(x));
    return r;
}
__device__ __forceinline__ void mma_tf32(
    float& c0, float& c1, float& c2, float& c3,
    uint32_t a0, uint32_t a1, uint32_t a2, uint32_t a3,
    uint32_t b0, uint32_t b1)
{
    asm volatile(
        "mma.sync.aligned.m16n8k8.row.col.f32.tf32.tf32.f32 "
        "{%0,%1,%2,%3}, {%4,%5,%6,%7}, {%8,%9}, {%0,%1,%2,%3};"
        : "+f"(c0), "+f"(c1), "+f"(c2), "+f"(c3)
        : "r"(a0), "r"(a1), "r"(a2), "r"(a3), "r"(b0), "r"(b1));
}

// ---------------------------------------------------------------------------
// Persistent per-layer GRU kernel (unchanged from round 4/5 passing version).
// ---------------------------------------------------------------------------
__global__ __launch_bounds__(NTHR, 1) void gru_layer_kernel(
    const float* __restrict__ Whh, const float* __restrict__ bhh, int ysel)
{
    extern __shared__ float sm[];
    float* W_s = sm;                      // HID*24 floats, k-major
    float* h_s = sm + HID * 24;           // 2*KC*BATCH floats

    const int tid = threadIdx.x;
    const int bid = blockIdx.x;
    const int c0  = bid * NCOLB;
    const int tn  = tid & 7;
    const int tm  = tid >> 3;
    const int c   = c0 + tn;
    const int b0  = tm * 2;

    for (int idx = tid; idx < 24 * HID; idx += NTHR) {
        int j = idx >> 10;
        int k = idx & (HID - 1);
        int jt = j / 3, jg = j - jt * 3;
        W_s[k * 24 + j] = Whh[(size_t)(jg * HID + c0 + jt) * HID + k];
    }

    const float bh0 = bhh[c];
    const float bh1 = bhh[HID + c];
    const float bh2 = bhh[2 * HID + c];

    float hprev0 = 0.f, hprev1 = 0.f;

    unsigned long long ep = *(volatile unsigned long long*)&g_bar_epoch;
    const uint32_t s_h = (uint32_t)__cvta_generic_to_shared(h_s);

    for (int t = 0; t < SEQ; t++) {
        const size_t r0 = ((size_t)b0 * SEQ + t) * G3;
        const size_t r1 = ((size_t)(b0 + 1) * SEQ + t) * G3;
        float x00 = __ldcg(&g_xg[r0 + c]);
        float x01 = __ldcg(&g_xg[r0 + HID + c]);
        float x02 = __ldcg(&g_xg[r0 + 2 * HID + c]);
        float x10 = __ldcg(&g_xg[r1 + c]);
        float x11 = __ldcg(&g_xg[r1 + HID + c]);
        float x12 = __ldcg(&g_xg[r1 + 2 * HID + c]);

        float a00 = 0.f, a01 = 0.f, a02 = 0.f;
        float a10 = 0.f, a11 = 0.f, a12 = 0.f;

        if (t > 0) {
#pragma unroll
            for (int ch = 0; ch < 2; ch++) {
                uint32_t dst = s_h + (uint32_t)(ch & 1) * (KC * BATCH * 4);
                const float* src = g_hT + (size_t)ch * KC * BATCH;
#pragma unroll
                for (int j = 0; j < (KC * BATCH) / (NTHR * 4); j++) {
                    int idx4 = tid + j * NTHR;
                    cp_async16(dst + (uint32_t)idx4 * 16, src + (size_t)idx4 * 4);
                }
                cp_commit();
            }

            for (int ch = 0; ch < HID / KC; ch++) {
                cp_wait1();
                __syncthreads();
                const float* hb = h_s + (ch & 1) * (KC * BATCH);
                const float* Wc = W_s + (size_t)ch * KC * 24;
#pragma unroll 8
                for (int k = 0; k < KC; k++) {
                    float2 a = *(const float2*)&hb[k * BATCH + b0];
                    float w0 = Wc[k * 24 + tn * 3 + 0];
                    float w1 = Wc[k * 24 + tn * 3 + 1];
                    float w2 = Wc[k * 24 + tn * 3 + 2];
                    a00 = fmaf(a.x, w0, a00);
                    a01 = fmaf(a.x, w1, a01);
                    a02 = fmaf(a.x, w2, a02);
                    a10 = fmaf(a.y, w0, a10);
                    a11 = fmaf(a.y, w1, a11);
                    a12 = fmaf(a.y, w2, a12);
                }
                __syncthreads();
                if (ch + 2 < HID / KC) {
                    uint32_t dst = s_h + (uint32_t)(ch & 1) * (KC * BATCH * 4);
                    const float* src = g_hT + (size_t)(ch + 2) * KC * BATCH;
#pragma unroll
                    for (int j = 0; j < (KC * BATCH) / (NTHR * 4); j++) {
                        int idx4 = tid + j * NTHR;
                        cp_async16(dst + (uint32_t)idx4 * 16, src + (size_t)idx4 * 4);
                    }
                }
                cp_commit();
            }
        }

        {
            float r  = fsigmoid(x00 + a00 + bh0);
            float z  = fsigmoid(x01 + a01 + bh1);
            float nn = ftanh(x02 + fmaf(r, a02 + bh2, 0.f));
            hprev0 = (1.f - z) * nn + z * hprev0;

            float r1g = fsigmoid(x10 + a10 + bh0);
            float z1g = fsigmoid(x11 + a11 + bh1);
            float n1g = ftanh(x12 + fmaf(r1g, a12 + bh2, 0.f));
            hprev1 = (1.f - z1g) * n1g + z1g * hprev1;
        }

        *(float2*)&g_hT[(size_t)c * BATCH + b0] = make_float2(hprev0, hprev1);

        if (ysel == 1) {
            g_yA[((size_t)b0 * SEQ + t) * HID + c]       = hprev0;
            g_yA[((size_t)(b0 + 1) * SEQ + t) * HID + c] = hprev1;
        } else if (ysel == 2) {
            g_yB[((size_t)b0 * SEQ + t) * HID + c]       = hprev0;
            g_yB[((size_t)(b0 + 1) * SEQ + t) * HID + c] = hprev1;
        }
        if (t == SEQ - 1) {
            g_hb[(size_t)b0 * HID + c]       = hprev0;
            g_hb[(size_t)(b0 + 1) * HID + c] = hprev1;
        }

        grid_barrier(++ep);
    }
}

// ---------------------------------------------------------------------------
// tf32 split-3 MMA GEMM for xg of layers 1,2 (K = 1024):
//   g_xg[m, n] = sum_k A[m,k] * W[n,k] + bias[n]
// Block tile 128(M) x 64(N), 4 warps (warp tile 64x32), mma.m16n8k8.tf32,
// 3-term split (hi*hi + hi*lo + lo*hi), cp.async double-buffered K=32 chunks.
// smem rows padded to 36 floats -> fragment lds are bank-conflict-free.
// ---------------------------------------------------------------------------
#define XKC   32
#define XLD   36
#define XA_F  (128 * XLD)      // floats per A stage
#define XB_F  (64 * XLD)       // floats per B stage
#define XST_F (XA_F + XB_F)    // floats per stage

__global__ __launch_bounds__(128, 2) void gemm_xg_tf32_kernel(
    int a_sel, const float* __restrict__ W, const float* __restrict__ bias)
{
    const float* A = (a_sel == 1) ? g_yA : g_yB;
    const int K = HID;

    extern __shared__ float xs[];        // 2 stages: [A(128x36) | B(64x36)]
    const int tid  = threadIdx.x;
    const int warp = tid >> 5;
    const int lane = tid & 31;
    const int g    = lane >> 2;          // group 0..7
    const int tq   = lane & 3;           // 0..3

    const int n0 = blockIdx.x * 64;
    const int m0 = blockIdx.y * 128;
    const int wm = (warp & 1) * 64;
    const int wn = (warp >> 1) * 32;

    const uint32_t s_base = (uint32_t)__cvta_generic_to_shared(xs);

    float acc[4][4][4];                  // [mi][ni][4 regs]
#pragma unroll
    for (int mi = 0; mi < 4; mi++)
#pragma unroll
        for (int ni = 0; ni < 4; ni++)
#pragma unroll
            for (int r = 0; r < 4; r++) acc[mi][ni][r] = 0.f;

    // ---- stage loader: A rows 128 x 8 segs, B rows 64 x 8 segs (16B each) ----
    auto load_stage = [&](int ch, int buf) {
        const int k0 = ch * XKC;
        uint32_t dstA = s_base + (uint32_t)buf * XST_F * 4;
        uint32_t dstB = dstA + XA_F * 4;
#pragma unroll
        for (int j = 0; j < 8; j++) {                 // 1024 A ops / 128 thr
            int o = tid + j * 128;
            int row = o >> 3, seg = o & 7;
            cp_async16(dstA + (uint32_t)(row * XLD + seg * 4) * 4,
                       A + (size_t)(m0 + row) * K + k0 + seg * 4);
        }
#pragma unroll
        for (int j = 0; j < 4; j++) {                 // 512 B ops / 128 thr
            int o = tid + j * 128;
            int row = o >> 3, seg = o & 7;
            cp_async16(dstB + (uint32_t)(row * XLD + seg * 4) * 4,
                       W + (size_t)(n0 + row) * K + k0 + seg * 4);
        }
    };

    const int NCH = K / XKC;             // 32
    load_stage(0, 0); cp_commit();
    load_stage(1, 1); cp_commit();

    for (int ch = 0; ch < NCH; ch++) {
        cp_wait1();
        __syncthreads();
        const float* As = xs + (ch & 1) * XST_F;
        const float* Bs = As + XA_F;

#pragma unroll
        for (int ks = 0; ks < 4; ks++) {
            const int k = ks * 8;
            // ---- A fragments: 4 m-tiles ----
            uint32_t ahi[4][4], alo[4][4];
#pragma unroll
            for (int mi = 0; mi < 4; mi++) {
                int rbase = wm + mi * 16 + g;
                float r0 = As[(rbase)     * XLD + k + tq];
                float r1 = As[(rbase + 8) * XLD + k + tq];
                float r2 = As[(rbase)     * XLD + k + tq + 4];
                float r3 = As[(rbase + 8) * XLD + k + tq + 4];
                ahi[mi][0] = f2tf32(r0); alo[mi][0] = f2tf32(r0 - __uint_as_float(ahi[mi][0]));
                ahi[mi][1] = f2tf32(r1); alo[mi][1] = f2tf32(r1 - __uint_as_float(ahi[mi][1]));
                ahi[mi][2] = f2tf32(r2); alo[mi][2] = f2tf32(r2 - __uint_as_float(ahi[mi][2]));
                ahi[mi][3] = f2tf32(r3); alo[mi][3] = f2tf32(r3 - __uint_as_float(ahi[mi][3]));
            }
            // ---- B fragments: 4 n-tiles ----
            uint32_t bhi[4][2], blo[4][2];
#pragma unroll
            for (int ni = 0; ni < 4; ni++) {
                int nbase = wn + ni * 8 + g;
                float r0 = Bs[nbase * XLD + k + tq];
                float r1 = Bs[nbase * XLD + k + tq + 4];
                bhi[ni][0] = f2tf32(r0); blo[ni][0] = f2tf32(r0 - __uint_as_float(bhi[ni][0]));
                bhi[ni][1] = f2tf32(r1); blo[ni][1] = f2tf32(r1 - __uint_as_float(bhi[ni][1]));
            }
            // ---- mma: hi*hi + hi*lo + lo*hi ----
#pragma unroll
            for (int mi = 0; mi < 4; mi++)
#pragma unroll
                for (int ni = 0; ni < 4; ni++) {
                    float* c = acc[mi][ni];
                    mma_tf32(c[0], c[1], c[2], c[3],
                             ahi[mi][0], ahi[mi][1], ahi[mi][2], ahi[mi][3],
                             bhi[ni][0], bhi[ni][1]);
                    mma_tf32(c[0], c[1], c[2], c[3],
                             ahi[mi][0], ahi[mi][1], ahi[mi][2], ahi[mi][3],
                             blo[ni][0], blo[ni][1]);
                    mma_tf32(c[0], c[1], c[2], c[3],
                             alo[mi][0], alo[mi][1], alo[mi][2], alo[mi][3],
                             bhi[ni][0], bhi[ni][1]);
                }
        }

        __syncthreads();
        if (ch + 2 < NCH) load_stage(ch + 2, ch & 1);
        cp_commit();
    }

    // ---- epilogue: add bias, store float2 pairs ----
#pragma unroll
    for (int mi = 0; mi < 4; mi++) {
        int r0 = m0 + wm + mi * 16 + g;
#pragma unroll
        for (int ni = 0; ni < 4; ni++) {
            int cb = n0 + wn + ni * 8 + 2 * tq;
            float2 bia = *(const float2*)&bias[cb];
            float* c = acc[mi][ni];
            *(float2*)&g_xg[(size_t)r0 * G3 + cb] =
                make_float2(c[0] + bia.x, c[1] + bia.y);
            *(float2*)&g_xg[(size_t)(r0 + 8) * G3 + cb] =
                make_float2(c[2] + bia.x, c[3] + bia.y);
        }
    }
}

// ---------------------------------------------------------------------------
// fp32 SGEMM for layer-0 xg (K = 118): unchanged proven kernel.
// ---------------------------------------------------------------------------
__global__ __launch_bounds__(256) void gemm_xg_kernel(
    const float* __restrict__ x_in, int K,
    const float* __restrict__ W, const float* __restrict__ bias)
{
    const float* A = x_in;

    __shared__ float As[8][128];
    __shared__ float Bs[8][128];

    const int n0 = blockIdx.x * 128;
    const int m0 = blockIdx.y * 128;
    const int tid = threadIdx.x;
    const int tx = tid & 15;
    const int ty = tid >> 4;

    float acc[8][8];
#pragma unroll
    for (int i = 0; i < 8; i++)
#pragma unroll
        for (int j = 0; j < 8; j++) acc[i][j] = 0.f;

    const int nkt = (K + 7) >> 3;
    for (int kt = 0; kt < nkt; kt++) {
        const int k0 = kt << 3;
#pragma unroll
        for (int i = 0; i < 4; i++) {
            int ii = tid + i * 256;
            int m = ii >> 3, k = ii & 7;
            As[k][m] = (k0 + k < K) ? A[(size_t)(m0 + m) * K + (k0 + k)] : 0.f;
        }
#pragma unroll
        for (int i = 0; i < 4; i++) {
            int ii = tid + i * 256;
            int n = ii >> 3, k = ii & 7;
            Bs[k][n] = (k0 + k < K) ? W[(size_t)(n0 + n) * K + (k0 + k)] : 0.f;
        }
        __syncthreads();
#pragma unroll
        for (int k = 0; k < 8; k++) {
            float a[8], b[8];
#pragma unroll
            for (int i = 0; i < 8; i++) a[i] = As[k][ty * 8 + i];
#pragma unroll
            for (int j = 0; j < 8; j++) b[j] = Bs[k][tx * 8 + j];
#pragma unroll
            for (int i = 0; i < 8; i++)
#pragma unroll
                for (int j = 0; j < 8; j++)
                    acc[i][j] = fmaf(a[i], b[j], acc[i][j]);
        }
        __syncthreads();
    }

#pragma unroll
    for (int i = 0; i < 8; i++) {
        size_t row = (size_t)(m0 + ty * 8 + i) * G3;
#pragma unroll
        for (int j = 0; j < 8; j++) {
            int n = n0 + tx * 8 + j;
            g_xg[row + n] = acc[i][j] + bias[n];
        }
    }
}

// ---------------------------------------------------------------------------
// Final linear: out[b] = dot(h_last[b,:], W_lin) + b_lin
// ---------------------------------------------------------------------------
__global__ __launch_bounds__(256) void final_kernel(
    const float* __restrict__ Wlin, const float* __restrict__ blin,
    float* __restrict__ out)
{
    const int b = blockIdx.x;
    const float* h = g_hb + b * HID;
    float s = 0.f;
    for (int k = threadIdx.x; k < HID; k += 256) s += h[k] * Wlin[k];
#pragma unroll
    for (int o = 16; o > 0; o >>= 1) s += __shfl_down_sync(0xffffffffu, s, o);
    __shared__ float red[8];
    if ((threadIdx.x & 31) == 0) red[threadIdx.x >> 5] = s;
    __syncthreads();
    if (threadIdx.x < 8) {
        s = red[threadIdx.x];
#pragma unroll
        for (int o = 4; o > 0; o >>= 1) s += __shfl_down_sync(0xffu, s, o);
        if (threadIdx.x == 0) out[b] = s + blin[0];
    }
}

// ---------------------------------------------------------------------------
extern "C" void kernel_launch(void* const* d_in, const int* in_sizes, int n_in,
                              void* d_out, int out_size)
{
    const float* x      = (const float*)d_in[0];
    const float* W_ih0  = (const float*)d_in[1];
    const float* W_ih12 = (const float*)d_in[2];
    const float* W_hh   = (const float*)d_in[3];
    const float* b_ih   = (const float*)d_in[4];
    const float* b_hh   = (const float*)d_in[5];
    const float* W_lin  = (const float*)d_in[6];
    const float* b_lin  = (const float*)d_in[7];
    float* out = (float*)d_out;

    const int smem_gru = (HID * 24 + 2 * KC * BATCH) * sizeof(float);   // 160 KB
    cudaFuncSetAttribute(gru_layer_kernel,
                         cudaFuncAttributeMaxDynamicSharedMemorySize, smem_gru);
    const int smem_xg = 2 * XST_F * sizeof(float);                      // 55296 B
    cudaFuncSetAttribute(gemm_xg_tf32_kernel,
                         cudaFuncAttributeMaxDynamicSharedMemorySize, smem_xg);

    for (int l = 0; l < 3; l++) {
        const int    ysel  = (l == 0) ? 1 : (l == 1 ? 2 : 0);
        const float* Whh_l = W_hh + (size_t)l * G3 * HID;
        const float* bih_l = b_ih + (size_t)l * G3;
        const float* bhh_l = b_hh + (size_t)l * G3;

        if (l == 0) {
            dim3 ggrid(G3 / 128, BT / 128);
            gemm_xg_kernel<<<ggrid, 256>>>(x, DIN0, W_ih0, bih_l);
        } else {
            const float* Wih = W_ih12 + (size_t)(l - 1) * G3 * HID;
            dim3 ggrid(G3 / 64, BT / 128);
            gemm_xg_tf32_kernel<<<ggrid, 128, smem_xg>>>(l, Wih, bih_l);
        }

        gru_layer_kernel<<<NBLK, NTHR, smem_gru>>>(Whh_l, bhh_l, ysel);
    }

    final_kernel<<<BATCH, 256>>>(W_lin, b_lin, out);
}

// round 7
// speedup vs baseline: 1.4618x; 1.1085x over previous
#include <cuda_runtime.h>
#include <cstdint>

#define HID   1024
#define BATCH 64
#define SEQ   512
#define G3    3072
#define BT    (BATCH * SEQ)
#define DIN0  118

#define NBLK  128          // persistent blocks (all co-resident; <= 148 SMs)
#define GNT   128          // threads in gru kernel (4 warps, 1/SMSP)
#define GKC   32           // k rows per h chunk
#define GHROW 68           // float2 per smem h k-row (64 + 4 pad)
#define GHBUF (GKC * GHROW)            // 2176 float2 per h buffer
#define GW2   (HID * 24)               // float2 for weight hi/lo slice
#define GSMF2 (GW2 + 2 * GHBUF)        // 28928 float2 = 231424 B

// ---------------- scratch (device globals; no allocation allowed) ----------
__device__ float  g_xg[(size_t)BT * G3];      // input projections for current layer
__device__ float  g_yA[(size_t)BT * HID];     // layer outputs ping
__device__ float  g_yB[(size_t)BT * HID];     // layer outputs pong
__device__ float2 g_hT2[2][HID * BATCH];      // hidden (tf32-hi, lo), [k][b], ping-pong
__device__ float  g_hb[BATCH * HID];          // final hidden, batch-major
__device__ unsigned long long g_bar_count;    // monotonic barrier arrivals
__device__ unsigned long long g_bar_epoch;    // monotonic barrier epoch

// ---------------------------------------------------------------------------
// software grid barrier (all NBLK blocks resident). Epochs absolute/monotonic.
// ---------------------------------------------------------------------------
__device__ __forceinline__ void grid_barrier(unsigned long long ep) {
    __threadfence();
    __syncthreads();
    if (threadIdx.x == 0) {
        unsigned long long total = atomicAdd(&g_bar_count, 1ull) + 1ull;
        if (total == ep * (unsigned long long)NBLK) {
            atomicExch(&g_bar_epoch, ep);     // release
        } else {
            while (*(volatile unsigned long long*)&g_bar_epoch < ep)
                __nanosleep(64);
        }
    }
    __syncthreads();
    __threadfence();
}

__device__ __forceinline__ float fsigmoid(float x) {
    return 1.f / (1.f + __expf(-x));
}
__device__ __forceinline__ float ftanh(float x) {
    return 2.f / (1.f + __expf(-2.f * x)) - 1.f;
}

// ---------------------------------------------------------------------------
// cp.async / tf32 helpers
// ---------------------------------------------------------------------------
__device__ __forceinline__ void cp_async16(uint32_t smem_dst, const void* gptr) {
    asm volatile("cp.async.cg.shared.global [%0], [%1], 16;\n"
                 :: "r"(smem_dst), "l"(gptr));
}
__device__ __forceinline__ void cp_commit() {
    asm volatile("cp.async.commit_group;\n");
}
__device__ __forceinline__ void cp_wait1() {
    asm volatile("cp.async.wait_group 1;\n");
}
__device__ __forceinline__ uint32_t f2tf32(float x) {
    uint32_t r;
    asm("cvt.rna.tf32.f32 %0, %1;" : "=r"(r) : "f"(x));
    return r;
}
__device__ __forceinline__ void mma_tf32(
    float& c0, float& c1, float& c2, float& c3,
    uint32_t a0, uint32_t a1, uint32_t a2, uint32_t a3,
    uint32_t b0, uint32_t b1)
{
    asm volatile(
        "mma.sync.aligned.m16n8k8.row.col.f32.tf32.tf32.f32 "
        "{%0,%1,%2,%3}, {%4,%5,%6,%7}, {%8,%9}, {%0,%1,%2,%3};"
        : "+f"(c0), "+f"(c1), "+f"(c2), "+f"(c3)
        : "r"(a0), "r"(a1), "r"(a2), "r"(a3), "r"(b0), "r"(b1));
}

// ---------------------------------------------------------------------------
// Persistent per-layer GRU kernel — tensor-core (tf32x3) recurrent GEMM.
// Block i owns HID cols c0..c0+7 (c0=8i) for all 3 gates: Whh rows
// { g*HID + c0 + jc }. smem:
//   W2 [k=0..1023][j=0..23] float2(hi,lo), j = gate*8 + col   (192 KB, resident)
//   h buffers: 2 x [GKC][GHROW] float2(hi,lo)                 (34.8 KB, cp.async DB)
// Warp g (of 4): m-tile g (batches 16g..16g+15), 3 n-tiles (= gates), K=1024.
// mma m16n8k8 tf32, 3-term split. Acc cells == gate cells -> gates in register.
// h ping-pong: step t reads g_hT2[t&1], writes g_hT2[(t+1)&1]. 1 barrier/step.
// ---------------------------------------------------------------------------
__global__ __launch_bounds__(GNT, 1) void gru_layer_kernel(
    const float* __restrict__ Whh, const float* __restrict__ bhh, int ysel)
{
    extern __shared__ float2 sm2[];
    float2* W2 = sm2;                    // GW2 float2
    float2* HB = sm2 + GW2;              // 2*GHBUF float2

    const int tid  = threadIdx.x;
    const int bid  = blockIdx.x;
    const int c0   = bid * 8;
    const int warp = tid >> 5;           // m-tile
    const int lane = tid & 31;
    const int l4   = lane >> 2;          // 0..7
    const int tq   = lane & 3;           // 0..3

    // ---- pre-split Whh slice into smem hi/lo (once) ----
    for (int idx = tid; idx < 24 * HID; idx += GNT) {
        int j = idx >> 10;               // 0..23 = gate*8 + col
        int k = idx & (HID - 1);
        int jg = j >> 3, jc = j & 7;
        float w  = Whh[(size_t)(jg * HID + c0 + jc) * HID + k];
        float wh = __uint_as_float(f2tf32(w));
        W2[k * 24 + j] = make_float2(wh, __uint_as_float(f2tf32(w - wh)));
    }

    // per-thread gate constants: cols cA, cA+1
    const int cA = c0 + 2 * tq;
    const int bA = warp * 16 + l4;       // rows bA, bA+8
    float bh[3][2];
#pragma unroll
    for (int gte = 0; gte < 3; gte++) {
        bh[gte][0] = bhh[gte * HID + cA];
        bh[gte][1] = bhh[gte * HID + cA + 1];
    }

    float hp[4] = {0.f, 0.f, 0.f, 0.f};  // h_prev cells (2 rows x 2 cols)

    unsigned long long ep = *(volatile unsigned long long*)&g_bar_epoch;
    const uint32_t s_hb = (uint32_t)__cvta_generic_to_shared(HB);

    for (int t = 0; t < SEQ; t++) {
        // ---- prefetch xg for this step's gate cells (12 values) ----
        const size_t rA = ((size_t)bA * SEQ + t) * G3;
        const size_t rB = ((size_t)(bA + 8) * SEQ + t) * G3;
        float xv[3][4];
#pragma unroll
        for (int gte = 0; gte < 3; gte++) {
            xv[gte][0] = __ldcg(&g_xg[rA + gte * HID + cA]);
            xv[gte][1] = __ldcg(&g_xg[rA + gte * HID + cA + 1]);
            xv[gte][2] = __ldcg(&g_xg[rB + gte * HID + cA]);
            xv[gte][3] = __ldcg(&g_xg[rB + gte * HID + cA + 1]);
        }

        float acc[3][4];
#pragma unroll
        for (int nt = 0; nt < 3; nt++)
#pragma unroll
            for (int r = 0; r < 4; r++) acc[nt][r] = 0.f;

        if (t > 0) {
            const float2* hsrc = g_hT2[t & 1];

            // stage chunks 0,1 (each: GKC k-rows x 64 float2, row pad to 68)
#pragma unroll
            for (int ch = 0; ch < 2; ch++) {
                uint32_t dst = s_hb + (uint32_t)(ch & 1) * (GHBUF * 8);
                const float2* src = hsrc + (size_t)ch * GKC * BATCH;
#pragma unroll
                for (int j = 0; j < (GKC * 32) / GNT; j++) {   // 8 ops/thread
                    int o = tid + j * GNT;
                    int k = o >> 5, s = o & 31;                // s = 16B seg
                    cp_async16(dst + (uint32_t)(k * GHROW + s * 2) * 8,
                               src + (size_t)k * BATCH + s * 2);
                }
                cp_commit();
            }

#pragma unroll 1
            for (int ch = 0; ch < HID / GKC; ch++) {
                cp_wait1();
                __syncthreads();
                const float2* hb = HB + (ch & 1) * GHBUF;
                const int kg = ch * GKC;

#pragma unroll
                for (int ks = 0; ks < GKC / 8; ks++) {
                    const int kk = ks * 8;
                    // A fragments (h): hi/lo pairs via float2 loads
                    float2 a0 = hb[(kk + tq) * GHROW + bA];
                    float2 a1 = hb[(kk + tq) * GHROW + bA + 8];
                    float2 a2 = hb[(kk + tq + 4) * GHROW + bA];
                    float2 a3 = hb[(kk + tq + 4) * GHROW + bA + 8];
                    uint32_t ah0 = __float_as_uint(a0.x), al0 = f2tf32(a0.y);
                    uint32_t ah1 = __float_as_uint(a1.x), al1 = f2tf32(a1.y);
                    uint32_t ah2 = __float_as_uint(a2.x), al2 = f2tf32(a2.y);
                    uint32_t ah3 = __float_as_uint(a3.x), al3 = f2tf32(a3.y);
#pragma unroll
                    for (int nt = 0; nt < 3; nt++) {
                        int j = nt * 8 + l4;
                        float2 b0 = W2[(kg + kk + tq) * 24 + j];
                        float2 b1 = W2[(kg + kk + tq + 4) * 24 + j];
                        uint32_t bh0 = __float_as_uint(b0.x), bl0 = __float_as_uint(b0.y);
                        uint32_t bh1 = __float_as_uint(b1.x), bl1 = __float_as_uint(b1.y);
                        float* c = acc[nt];
                        mma_tf32(c[0], c[1], c[2], c[3], ah0, ah1, ah2, ah3, bh0, bh1);
                        mma_tf32(c[0], c[1], c[2], c[3], ah0, ah1, ah2, ah3, bl0, bl1);
                        mma_tf32(c[0], c[1], c[2], c[3], al0, al1, al2, al3, bh0, bh1);
                    }
                }
                __syncthreads();
                if (ch + 2 < HID / GKC) {
                    uint32_t dst = s_hb + (uint32_t)(ch & 1) * (GHBUF * 8);
                    const float2* src = hsrc + (size_t)(ch + 2) * GKC * BATCH;
#pragma unroll
                    for (int j = 0; j < (GKC * 32) / GNT; j++) {
                        int o = tid + j * GNT;
                        int k = o >> 5, s = o & 31;
                        cp_async16(dst + (uint32_t)(k * GHROW + s * 2) * 8,
                                   src + (size_t)k * BATCH + s * 2);
                    }
                }
                cp_commit();    // (possibly empty) keeps wait_group math uniform
            }
        }

        // ---- gates, fully in register (cell r: row i = r>>1, col jj = r&1) ----
        float2* hdst = g_hT2[(t + 1) & 1];
#pragma unroll
        for (int r = 0; r < 4; r++) {
            int i  = r >> 1, jj = r & 1;
            int b  = bA + 8 * i;
            int cc = cA + jj;
            int ar = 2 * i + jj;          // mma acc register index for this cell
            float rg = fsigmoid(xv[0][2 * i + jj] + acc[0][ar] + bh[0][jj]);
            float zg = fsigmoid(xv[1][2 * i + jj] + acc[1][ar] + bh[1][jj]);
            float ng = ftanh(xv[2][2 * i + jj] + rg * (acc[2][ar] + bh[2][jj]));
            float h  = (1.f - zg) * ng + zg * hp[r];
            hp[r] = h;

            float hh = __uint_as_float(f2tf32(h));
            hdst[(size_t)cc * BATCH + b] = make_float2(hh, h - hh);

            size_t bt = (size_t)b * SEQ + t;
            if (ysel == 1)      g_yA[bt * HID + cc] = h;
            else if (ysel == 2) g_yB[bt * HID + cc] = h;
            if (t == SEQ - 1)   g_hb[(size_t)b * HID + cc] = h;
        }

        grid_barrier(++ep);
    }
}

// ---------------------------------------------------------------------------
// tf32 split-3 MMA GEMM for xg of layers 1,2 (K = 1024). (unchanged, passing)
// ---------------------------------------------------------------------------
#define XKC   32
#define XLD   36
#define XA_F  (128 * XLD)
#define XB_F  (64 * XLD)
#define XST_F (XA_F + XB_F)

__global__ __launch_bounds__(128, 2) void gemm_xg_tf32_kernel(
    int a_sel, const float* __restrict__ W, const float* __restrict__ bias)
{
    const float* A = (a_sel == 1) ? g_yA : g_yB;
    const int K = HID;

    extern __shared__ float xs[];
    const int tid  = threadIdx.x;
    const int warp = tid >> 5;
    const int lane = tid & 31;
    const int g    = lane >> 2;
    const int tq   = lane & 3;

    const int n0 = blockIdx.x * 64;
    const int m0 = blockIdx.y * 128;
    const int wm = (warp & 1) * 64;
    const int wn = (warp >> 1) * 32;

    const uint32_t s_base = (uint32_t)__cvta_generic_to_shared(xs);

    float acc[4][4][4];
#pragma unroll
    for (int mi = 0; mi < 4; mi++)
#pragma unroll
        for (int ni = 0; ni < 4; ni++)
#pragma unroll
            for (int r = 0; r < 4; r++) acc[mi][ni][r] = 0.f;

    auto load_stage = [&](int ch, int buf) {
        const int k0 = ch * XKC;
        uint32_t dstA = s_base + (uint32_t)buf * XST_F * 4;
        uint32_t dstB = dstA + XA_F * 4;
#pragma unroll
        for (int j = 0; j < 8; j++) {
            int o = tid + j * 128;
            int row = o >> 3, seg = o & 7;
            cp_async16(dstA + (uint32_t)(row * XLD + seg * 4) * 4,
                       A + (size_t)(m0 + row) * K + k0 + seg * 4);
        }
#pragma unroll
        for (int j = 0; j < 4; j++) {
            int o = tid + j * 128;
            int row = o >> 3, seg = o & 7;
            cp_async16(dstB + (uint32_t)(row * XLD + seg * 4) * 4,
                       W + (size_t)(n0 + row) * K + k0 + seg * 4);
        }
    };

    const int NCH = K / XKC;
    load_stage(0, 0); cp_commit();
    load_stage(1, 1); cp_commit();

    for (int ch = 0; ch < NCH; ch++) {
        cp_wait1();
        __syncthreads();
        const float* As = xs + (ch & 1) * XST_F;
        const float* Bs = As + XA_F;

#pragma unroll
        for (int ks = 0; ks < 4; ks++) {
            const int k = ks * 8;
            uint32_t ahi[4][4], alo[4][4];
#pragma unroll
            for (int mi = 0; mi < 4; mi++) {
                int rbase = wm + mi * 16 + g;
                float r0 = As[(rbase)     * XLD + k + tq];
                float r1 = As[(rbase + 8) * XLD + k + tq];
                float r2 = As[(rbase)     * XLD + k + tq + 4];
                float r3 = As[(rbase + 8) * XLD + k + tq + 4];
                ahi[mi][0] = f2tf32(r0); alo[mi][0] = f2tf32(r0 - __uint_as_float(ahi[mi][0]));
                ahi[mi][1] = f2tf32(r1); alo[mi][1] = f2tf32(r1 - __uint_as_float(ahi[mi][1]));
                ahi[mi][2] = f2tf32(r2); alo[mi][2] = f2tf32(r2 - __uint_as_float(ahi[mi][2]));
                ahi[mi][3] = f2tf32(r3); alo[mi][3] = f2tf32(r3 - __uint_as_float(ahi[mi][3]));
            }
            uint32_t bhi[4][2], blo[4][2];
#pragma unroll
            for (int ni = 0; ni < 4; ni++) {
                int nbase = wn + ni * 8 + g;
                float r0 = Bs[nbase * XLD + k + tq];
                float r1 = Bs[nbase * XLD + k + tq + 4];
                bhi[ni][0] = f2tf32(r0); blo[ni][0] = f2tf32(r0 - __uint_as_float(bhi[ni][0]));
                bhi[ni][1] = f2tf32(r1); blo[ni][1] = f2tf32(r1 - __uint_as_float(bhi[ni][1]));
            }
#pragma unroll
            for (int mi = 0; mi < 4; mi++)
#pragma unroll
                for (int ni = 0; ni < 4; ni++) {
                    float* c = acc[mi][ni];
                    mma_tf32(c[0], c[1], c[2], c[3],
                             ahi[mi][0], ahi[mi][1], ahi[mi][2], ahi[mi][3],
                             bhi[ni][0], bhi[ni][1]);
                    mma_tf32(c[0], c[1], c[2], c[3],
                             ahi[mi][0], ahi[mi][1], ahi[mi][2], ahi[mi][3],
                             blo[ni][0], blo[ni][1]);
                    mma_tf32(c[0], c[1], c[2], c[3],
                             alo[mi][0], alo[mi][1], alo[mi][2], alo[mi][3],
                             bhi[ni][0], bhi[ni][1]);
                }
        }

        __syncthreads();
        if (ch + 2 < NCH) load_stage(ch + 2, ch & 1);
        cp_commit();
    }

#pragma unroll
    for (int mi = 0; mi < 4; mi++) {
        int r0 = m0 + wm + mi * 16 + g;
#pragma unroll
        for (int ni = 0; ni < 4; ni++) {
            int cb = n0 + wn + ni * 8 + 2 * tq;
            float2 bia = *(const float2*)&bias[cb];
            float* c = acc[mi][ni];
            *(float2*)&g_xg[(size_t)r0 * G3 + cb] =
                make_float2(c[0] + bia.x, c[1] + bia.y);
            *(float2*)&g_xg[(size_t)(r0 + 8) * G3 + cb] =
                make_float2(c[2] + bia.x, c[3] + bia.y);
        }
    }
}

// ---------------------------------------------------------------------------
// fp32 SGEMM for layer-0 xg (K = 118). (unchanged, passing)
// ---------------------------------------------------------------------------
__global__ __launch_bounds__(256) void gemm_xg_kernel(
    const float* __restrict__ x_in, int K,
    const float* __restrict__ W, const float* __restrict__ bias)
{
    const float* A = x_in;

    __shared__ float As[8][128];
    __shared__ float Bs[8][128];

    const int n0 = blockIdx.x * 128;
    const int m0 = blockIdx.y * 128;
    const int tid = threadIdx.x;
    const int tx = tid & 15;
    const int ty = tid >> 4;

    float acc[8][8];
#pragma unroll
    for (int i = 0; i < 8; i++)
#pragma unroll
        for (int j = 0; j < 8; j++) acc[i][j] = 0.f;

    const int nkt = (K + 7) >> 3;
    for (int kt = 0; kt < nkt; kt++) {
        const int k0 = kt << 3;
#pragma unroll
        for (int i = 0; i < 4; i++) {
            int ii = tid + i * 256;
            int m = ii >> 3, k = ii & 7;
            As[k][m] = (k0 + k < K) ? A[(size_t)(m0 + m) * K + (k0 + k)] : 0.f;
        }
#pragma unroll
        for (int i = 0; i < 4; i++) {
            int ii = tid + i * 256;
            int n = ii >> 3, k = ii & 7;
            Bs[k][n] = (k0 + k < K) ? W[(size_t)(n0 + n) * K + (k0 + k)] : 0.f;
        }
        __syncthreads();
#pragma unroll
        for (int k = 0; k < 8; k++) {
            float a[8], b[8];
#pragma unroll
            for (int i = 0; i < 8; i++) a[i] = As[k][ty * 8 + i];
#pragma unroll
            for (int j = 0; j < 8; j++) b[j] = Bs[k][tx * 8 + j];
#pragma unroll
            for (int i = 0; i < 8; i++)
#pragma unroll
                for (int j = 0; j < 8; j++)
                    acc[i][j] = fmaf(a[i], b[j], acc[i][j]);
        }
        __syncthreads();
    }

#pragma unroll
    for (int i = 0; i < 8; i++) {
        size_t row = (size_t)(m0 + ty * 8 + i) * G3;
#pragma unroll
        for (int j = 0; j < 8; j++) {
            int n = n0 + tx * 8 + j;
            g_xg[row + n] = acc[i][j] + bias[n];
        }
    }
}

// ---------------------------------------------------------------------------
// Final linear: out[b] = dot(h_last[b,:], W_lin) + b_lin
// ---------------------------------------------------------------------------
__global__ __launch_bounds__(256) void final_kernel(
    const float* __restrict__ Wlin, const float* __restrict__ blin,
    float* __restrict__ out)
{
    const int b = blockIdx.x;
    const float* h = g_hb + b * HID;
    float s = 0.f;
    for (int k = threadIdx.x; k < HID; k += 256) s += h[k] * Wlin[k];
#pragma unroll
    for (int o = 16; o > 0; o >>= 1) s += __shfl_down_sync(0xffffffffu, s, o);
    __shared__ float red[8];
    if ((threadIdx.x & 31) == 0) red[threadIdx.x >> 5] = s;
    __syncthreads();
    if (threadIdx.x < 8) {
        s = red[threadIdx.x];
#pragma unroll
        for (int o = 4; o > 0; o >>= 1) s += __shfl_down_sync(0xffu, s, o);
        if (threadIdx.x == 0) out[b] = s + blin[0];
    }
}

// ---------------------------------------------------------------------------
extern "C" void kernel_launch(void* const* d_in, const int* in_sizes, int n_in,
                              void* d_out, int out_size)
{
    const float* x      = (const float*)d_in[0];
    const float* W_ih0  = (const float*)d_in[1];
    const float* W_ih12 = (const float*)d_in[2];
    const float* W_hh   = (const float*)d_in[3];
    const float* b_ih   = (const float*)d_in[4];
    const float* b_hh   = (const float*)d_in[5];
    const float* W_lin  = (const float*)d_in[6];
    const float* b_lin  = (const float*)d_in[7];
    float* out = (float*)d_out;

    const int smem_gru = GSMF2 * sizeof(float2);     // 231424 B
    cudaFuncSetAttribute(gru_layer_kernel,
                         cudaFuncAttributeMaxDynamicSharedMemorySize, smem_gru);
    const int smem_xg = 2 * XST_F * sizeof(float);   // 55296 B
    cudaFuncSetAttribute(gemm_xg_tf32_kernel,
                         cudaFuncAttributeMaxDynamicSharedMemorySize, smem_xg);

    for (int l = 0; l < 3; l++) {
        const int    ysel  = (l == 0) ? 1 : (l == 1 ? 2 : 0);
        const float* Whh_l = W_hh + (size_t)l * G3 * HID;
        const float* bih_l = b_ih + (size_t)l * G3;
        const float* bhh_l = b_hh + (size_t)l * G3;

        if (l == 0) {
            dim3 ggrid(G3 / 128, BT / 128);
            gemm_xg_kernel<<<ggrid, 256>>>(x, DIN0, W_ih0, bih_l);
        } else {
            const float* Wih = W_ih12 + (size_t)(l - 1) * G3 * HID;
            dim3 ggrid(G3 / 64, BT / 128);
            gemm_xg_tf32_kernel<<<ggrid, 128, smem_xg>>>(l, Wih, bih_l);
        }

        gru_layer_kernel<<<NBLK, GNT, smem_gru>>>(Whh_l, bhh_l, ysel);
    }

    final_kernel<<<BATCH, 256>>>(W_lin, b_lin, out);
}

// round 8
// speedup vs baseline: 1.6443x; 1.1248x over previous
#include <cuda_runtime.h>
#include <cstdint>

#define HID   1024
#define BATCH 64
#define SEQ   512
#define G3    3072
#define BT    (BATCH * SEQ)
#define DIN0  118

#define NBLK  128          // persistent blocks (all co-resident; <= 148 SMs)
#define GNT   256          // 8 warps: wg0 = warps 0-3, wg1 = warps 4-7
#define GKC   64           // k rows per staged h chunk (each wg computes 32)
#define GHROW 68           // floats per smem h k-row (64 + 4 pad)
#define GW2   (HID * 24)   // float2 for weight hi/lo slice
// smem bytes: W2 (192 KB) + 2 h buffers (2*64*68*4 = 34816) = 231424
#define GSM_BYTES (GW2 * 8 + 2 * GKC * GHROW * 4)

// ---------------- scratch (device globals; no allocation allowed) ----------
__device__ float  g_xg[(size_t)BT * G3];      // input projections for current layer
__device__ float  g_yA[(size_t)BT * HID];     // layer outputs ping
__device__ float  g_yB[(size_t)BT * HID];     // layer outputs pong
__device__ float  g_hT[2][HID * BATCH];       // hidden fp32, [k][b], ping-pong
__device__ float  g_hb[BATCH * HID];          // final hidden, batch-major
__device__ unsigned long long g_flags[NBLK * 16];  // barrier flags, 128B stride
__device__ unsigned long long g_bar_epoch;         // barrier epoch broadcast

// ---------------------------------------------------------------------------
// flag-tree grid barrier: per-block flag stores (parallel) -> block 0 gathers
// -> epoch broadcast. Avoids the 128-way same-address atomic serialization.
// Epochs absolute/monotonic across launches (64-bit).
// ---------------------------------------------------------------------------
__device__ __forceinline__ void grid_barrier(unsigned long long ep) {
    const int tid = threadIdx.x;
    const int bid = blockIdx.x;
    __threadfence();
    __syncthreads();                       // all block threads' writes fenced
    if (tid == 0)
        *(volatile unsigned long long*)&g_flags[bid * 16] = ep;
    if (bid == 0) {
        if (tid < NBLK) {
            while (*(volatile unsigned long long*)&g_flags[tid * 16] < ep)
                __nanosleep(32);
        }
        __syncthreads();                   // block 0: all flags seen
        if (tid == 0) {
            __threadfence();
            *(volatile unsigned long long*)&g_bar_epoch = ep;
        }
    }
    if (tid == 0) {
        while (*(volatile unsigned long long*)&g_bar_epoch < ep)
            __nanosleep(32);
    }
    __syncthreads();
    __threadfence();
}

__device__ __forceinline__ float fsigmoid(float x) {
    return 1.f / (1.f + __expf(-x));
}
__device__ __forceinline__ float ftanh(float x) {
    return 2.f / (1.f + __expf(-2.f * x)) - 1.f;
}

// ---------------------------------------------------------------------------
// cp.async / tf32 helpers
// ---------------------------------------------------------------------------
__device__ __forceinline__ void cp_async16(uint32_t smem_dst, const void* gptr) {
    asm volatile("cp.async.cg.shared.global [%0], [%1], 16;\n"
                 :: "r"(smem_dst), "l"(gptr));
}
__device__ __forceinline__ void cp_commit() {
    asm volatile("cp.async.commit_group;\n");
}
__device__ __forceinline__ void cp_wait1() {
    asm volatile("cp.async.wait_group 1;\n");
}
__device__ __forceinline__ void cp_wait0() {
    asm volatile("cp.async.wait_group 0;\n");
}
__device__ __forceinline__ uint32_t f2tf32(float x) {
    uint32_t r;
    asm("cvt.rna.tf32.f32 %0, %1;" : "=r"(r) : "f"(x));
    return r;
}
__device__ __forceinline__ void mma_tf32(
    float& c0, float& c1, float& c2, float& c3,
    uint32_t a0, uint32_t a1, uint32_t a2, uint32_t a3,
    uint32_t b0, uint32_t b1)
{
    asm volatile(
        "mma.sync.aligned.m16n8k8.row.col.f32.tf32.tf32.f32 "
        "{%0,%1,%2,%3}, {%4,%5,%6,%7}, {%8,%9}, {%0,%1,%2,%3};"
        : "+f"(c0), "+f"(c1), "+f"(c2), "+f"(c3)
        : "r"(a0), "r"(a1), "r"(a2), "r"(a3), "r"(b0), "r"(b1));
}

// ---------------------------------------------------------------------------
// Persistent per-layer GRU kernel — tf32x3 mma recurrent GEMM, 8 warps.
// Block i owns HID cols c0..c0+7 (c0=8i) for all 3 gates.
//   smem: W2[k=0..1023][j=0..23] float2(hi,lo), j = gate*8+col (192 KB resident)
//         h: 2 x [GKC=64 k-rows][68 floats] fp32 staging (34 KB, cp.async DB)
// Warp w: m-tile (w&3) [batches 16(w&3)..+15], k-half (w>>2) of each chunk.
// Per step: GEMM (16 chunks x 4 ks each wg) -> wg1 acc -> smem -> wg0 adds,
// gates in register (wg0 only), h fp32 ping-pong, ONE flag-tree barrier.
// ---------------------------------------------------------------------------
__global__ __launch_bounds__(GNT, 1) void gru_layer_kernel(
    const float* __restrict__ Whh, const float* __restrict__ bhh, int ysel)
{
    extern __shared__ float2 sm2[];
    float2* W2  = sm2;                         // GW2 float2
    float*  HBf = (float*)(sm2 + GW2);         // 2 * GKC * GHROW floats

    const int tid  = threadIdx.x;
    const int bid  = blockIdx.x;
    const int c0   = bid * 8;
    const int warp = tid >> 5;
    const int lane = tid & 31;
    const int mt   = warp & 3;                 // m-tile
    const int wgk  = warp >> 2;                // k-half within chunk
    const int l4   = lane >> 2;                // 0..7
    const int tq   = lane & 3;                 // 0..3

    // ---- pre-split Whh slice into smem hi/lo (once) ----
    for (int idx = tid; idx < 24 * HID; idx += GNT) {
        int j = idx >> 10;                     // 0..23 = gate*8 + col
        int k = idx & (HID - 1);
        int jg = j >> 3, jc = j & 7;
        float w  = Whh[(size_t)(jg * HID + c0 + jc) * HID + k];
        float wh = __uint_as_float(f2tf32(w));
        W2[k * 24 + j] = make_float2(wh, __uint_as_float(f2tf32(w - wh)));
    }

    // gate constants (used by wg0 only)
    const int cA = c0 + 2 * tq;
    const int bA = mt * 16 + l4;
    float bh[3][2];
#pragma unroll
    for (int gte = 0; gte < 3; gte++) {
        bh[gte][0] = bhh[gte * HID + cA];
        bh[gte][1] = bhh[gte * HID + cA + 1];
    }

    float hp[4] = {0.f, 0.f, 0.f, 0.f};        // h_prev cells (wg0)

    unsigned long long ep = *(volatile unsigned long long*)&g_bar_epoch;
    const uint32_t s_hb = (uint32_t)__cvta_generic_to_shared(HBf);

    for (int t = 0; t < SEQ; t++) {
        // ---- prefetch xg for this step's gate cells (wg0 only) ----
        float xv[3][4];
        if (wgk == 0) {
            const size_t rA = ((size_t)bA * SEQ + t) * G3;
            const size_t rB = ((size_t)(bA + 8) * SEQ + t) * G3;
#pragma unroll
            for (int gte = 0; gte < 3; gte++) {
                xv[gte][0] = __ldcg(&g_xg[rA + gte * HID + cA]);
                xv[gte][1] = __ldcg(&g_xg[rA + gte * HID + cA + 1]);
                xv[gte][2] = __ldcg(&g_xg[rB + gte * HID + cA]);
                xv[gte][3] = __ldcg(&g_xg[rB + gte * HID + cA + 1]);
            }
        }

        float acc[3][4];
#pragma unroll
        for (int nt = 0; nt < 3; nt++)
#pragma unroll
            for (int r = 0; r < 4; r++) acc[nt][r] = 0.f;

        if (t > 0) {
            const float* hsrc = g_hT[t & 1];

            // stage chunks 0,1: 64 k-rows x 64 floats, rows padded to 68
#pragma unroll
            for (int ch = 0; ch < 2; ch++) {
                uint32_t dst = s_hb + (uint32_t)(ch & 1) * (GKC * GHROW * 4);
                const float* src = hsrc + (size_t)ch * GKC * BATCH;
#pragma unroll
                for (int j = 0; j < (GKC * 16) / GNT; j++) {   // 4 ops/thread
                    int o = tid + j * GNT;
                    int k = o >> 4, s = o & 15;                // s = 16B seg
                    cp_async16(dst + (uint32_t)(k * GHROW + s * 4) * 4,
                               src + (size_t)k * BATCH + s * 4);
                }
                cp_commit();
            }

#pragma unroll 1
            for (int ch = 0; ch < HID / GKC; ch++) {           // 16 chunks
                cp_wait1();
                __syncthreads();
                const float* hb = HBf + (ch & 1) * (GKC * GHROW) + wgk * 32 * GHROW;
                const int kg = ch * GKC + wgk * 32;

#pragma unroll
                for (int ks = 0; ks < 4; ks++) {
                    const int kk = ks * 8;
                    // A fragments (h fp32 -> hi/lo on the fly)
                    float a0 = hb[(kk + tq) * GHROW + bA];
                    float a1 = hb[(kk + tq) * GHROW + bA + 8];
                    float a2 = hb[(kk + tq + 4) * GHROW + bA];
                    float a3 = hb[(kk + tq + 4) * GHROW + bA + 8];
                    uint32_t ah0 = f2tf32(a0), al0 = f2tf32(a0 - __uint_as_float(ah0));
                    uint32_t ah1 = f2tf32(a1), al1 = f2tf32(a1 - __uint_as_float(ah1));
                    uint32_t ah2 = f2tf32(a2), al2 = f2tf32(a2 - __uint_as_float(ah2));
                    uint32_t ah3 = f2tf32(a3), al3 = f2tf32(a3 - __uint_as_float(ah3));
#pragma unroll
                    for (int nt = 0; nt < 3; nt++) {
                        int j = nt * 8 + l4;
                        float2 b0 = W2[(kg + kk + tq) * 24 + j];
                        float2 b1 = W2[(kg + kk + tq + 4) * 24 + j];
                        uint32_t bh0 = __float_as_uint(b0.x), bl0 = __float_as_uint(b0.y);
                        uint32_t bh1 = __float_as_uint(b1.x), bl1 = __float_as_uint(b1.y);
                        float* c = acc[nt];
                        mma_tf32(c[0], c[1], c[2], c[3], ah0, ah1, ah2, ah3, bh0, bh1);
                        mma_tf32(c[0], c[1], c[2], c[3], ah0, ah1, ah2, ah3, bl0, bl1);
                        mma_tf32(c[0], c[1], c[2], c[3], al0, al1, al2, al3, bh0, bh1);
                    }
                }
                __syncthreads();
                if (ch + 2 < HID / GKC) {
                    uint32_t dst = s_hb + (uint32_t)(ch & 1) * (GKC * GHROW * 4);
                    const float* src = hsrc + (size_t)(ch + 2) * GKC * BATCH;
#pragma unroll
                    for (int j = 0; j < (GKC * 16) / GNT; j++) {
                        int o = tid + j * GNT;
                        int k = o >> 4, s = o & 15;
                        cp_async16(dst + (uint32_t)(k * GHROW + s * 4) * 4,
                                   src + (size_t)k * BATCH + s * 4);
                    }
                }
                cp_commit();
            }

            // ---- cross-warpgroup acc reduction (reuse h staging as scratch) --
            cp_wait0();
            __syncthreads();
            float* red = HBf;                  // 128 threads x 12 floats
            if (wgk == 1) {
                int o = (mt * 32 + lane) * 12;
#pragma unroll
                for (int nt = 0; nt < 3; nt++)
#pragma unroll
                    for (int r = 0; r < 4; r++)
                        red[o + nt * 4 + r] = acc[nt][r];
            }
            __syncthreads();
            if (wgk == 0) {
                int o = (mt * 32 + lane) * 12;
#pragma unroll
                for (int nt = 0; nt < 3; nt++)
#pragma unroll
                    for (int r = 0; r < 4; r++)
                        acc[nt][r] += red[o + nt * 4 + r];
            }
        }

        // ---- gates, in register (wg0 only) ----
        if (wgk == 0) {
            float* hdst = g_hT[(t + 1) & 1];
#pragma unroll
            for (int r = 0; r < 4; r++) {
                int i  = r >> 1, jj = r & 1;
                int b  = bA + 8 * i;
                int cc = cA + jj;
                int ar = 2 * i + jj;
                float rg = fsigmoid(xv[0][2 * i + jj] + acc[0][ar] + bh[0][jj]);
                float zg = fsigmoid(xv[1][2 * i + jj] + acc[1][ar] + bh[1][jj]);
                float ng = ftanh(xv[2][2 * i + jj] + rg * (acc[2][ar] + bh[2][jj]));
                float h  = (1.f - zg) * ng + zg * hp[r];
                hp[r] = h;

                hdst[(size_t)cc * BATCH + b] = h;

                size_t bt = (size_t)b * SEQ + t;
                if (ysel == 1)      g_yA[bt * HID + cc] = h;
                else if (ysel == 2) g_yB[bt * HID + cc] = h;
                if (t == SEQ - 1)   g_hb[(size_t)b * HID + cc] = h;
            }
        }

        grid_barrier(++ep);
    }
}

// ---------------------------------------------------------------------------
// tf32 split-3 MMA GEMM for xg of layers 1,2 (K = 1024). (unchanged, passing)
// ---------------------------------------------------------------------------
#define XKC   32
#define XLD   36
#define XA_F  (128 * XLD)
#define XB_F  (64 * XLD)
#define XST_F (XA_F + XB_F)

__global__ __launch_bounds__(128, 2) void gemm_xg_tf32_kernel(
    int a_sel, const float* __restrict__ W, const float* __restrict__ bias)
{
    const float* A = (a_sel == 1) ? g_yA : g_yB;
    const int K = HID;

    extern __shared__ float xs[];
    const int tid  = threadIdx.x;
    const int warp = tid >> 5;
    const int lane = tid & 31;
    const int g    = lane >> 2;
    const int tq   = lane & 3;

    const int n0 = blockIdx.x * 64;
    const int m0 = blockIdx.y * 128;
    const int wm = (warp & 1) * 64;
    const int wn = (warp >> 1) * 32;

    const uint32_t s_base = (uint32_t)__cvta_generic_to_shared(xs);

    float acc[4][4][4];
#pragma unroll
    for (int mi = 0; mi < 4; mi++)
#pragma unroll
        for (int ni = 0; ni < 4; ni++)
#pragma unroll
            for (int r = 0; r < 4; r++) acc[mi][ni][r] = 0.f;

    auto load_stage = [&](int ch, int buf) {
        const int k0 = ch * XKC;
        uint32_t dstA = s_base + (uint32_t)buf * XST_F * 4;
        uint32_t dstB = dstA + XA_F * 4;
#pragma unroll
        for (int j = 0; j < 8; j++) {
            int o = tid + j * 128;
            int row = o >> 3, seg = o & 7;
            cp_async16(dstA + (uint32_t)(row * XLD + seg * 4) * 4,
                       A + (size_t)(m0 + row) * K + k0 + seg * 4);
        }
#pragma unroll
        for (int j = 0; j < 4; j++) {
            int o = tid + j * 128;
            int row = o >> 3, seg = o & 7;
            cp_async16(dstB + (uint32_t)(row * XLD + seg * 4) * 4,
                       W + (size_t)(n0 + row) * K + k0 + seg * 4);
        }
    };

    const int NCH = K / XKC;
    load_stage(0, 0); cp_commit();
    load_stage(1, 1); cp_commit();

    for (int ch = 0; ch < NCH; ch++) {
        cp_wait1();
        __syncthreads();
        const float* As = xs + (ch & 1) * XST_F;
        const float* Bs = As + XA_F;

#pragma unroll
        for (int ks = 0; ks < 4; ks++) {
            const int k = ks * 8;
            uint32_t ahi[4][4], alo[4][4];
#pragma unroll
            for (int mi = 0; mi < 4; mi++) {
                int rbase = wm + mi * 16 + g;
                float r0 = As[(rbase)     * XLD + k + tq];
                float r1 = As[(rbase + 8) * XLD + k + tq];
                float r2 = As[(rbase)     * XLD + k + tq + 4];
                float r3 = As[(rbase + 8) * XLD + k + tq + 4];
                ahi[mi][0] = f2tf32(r0); alo[mi][0] = f2tf32(r0 - __uint_as_float(ahi[mi][0]));
                ahi[mi][1] = f2tf32(r1); alo[mi][1] = f2tf32(r1 - __uint_as_float(ahi[mi][1]));
                ahi[mi][2] = f2tf32(r2); alo[mi][2] = f2tf32(r2 - __uint_as_float(ahi[mi][2]));
                ahi[mi][3] = f2tf32(r3); alo[mi][3] = f2tf32(r3 - __uint_as_float(ahi[mi][3]));
            }
            uint32_t bhi[4][2], blo[4][2];
#pragma unroll
            for (int ni = 0; ni < 4; ni++) {
                int nbase = wn + ni * 8 + g;
                float r0 = Bs[nbase * XLD + k + tq];
                float r1 = Bs[nbase * XLD + k + tq + 4];
                bhi[ni][0] = f2tf32(r0); blo[ni][0] = f2tf32(r0 - __uint_as_float(bhi[ni][0]));
                bhi[ni][1] = f2tf32(r1); blo[ni][1] = f2tf32(r1 - __uint_as_float(bhi[ni][1]));
            }
#pragma unroll
            for (int mi = 0; mi < 4; mi++)
#pragma unroll
                for (int ni = 0; ni < 4; ni++) {
                    float* c = acc[mi][ni];
                    mma_tf32(c[0], c[1], c[2], c[3],
                             ahi[mi][0], ahi[mi][1], ahi[mi][2], ahi[mi][3],
                             bhi[ni][0], bhi[ni][1]);
                    mma_tf32(c[0], c[1], c[2], c[3],
                             ahi[mi][0], ahi[mi][1], ahi[mi][2], ahi[mi][3],
                             blo[ni][0], blo[ni][1]);
                    mma_tf32(c[0], c[1], c[2], c[3],
                             alo[mi][0], alo[mi][1], alo[mi][2], alo[mi][3],
                             bhi[ni][0], bhi[ni][1]);
                }
        }

        __syncthreads();
        if (ch + 2 < NCH) load_stage(ch + 2, ch & 1);
        cp_commit();
    }

#pragma unroll
    for (int mi = 0; mi < 4; mi++) {
        int r0 = m0 + wm + mi * 16 + g;
#pragma unroll
        for (int ni = 0; ni < 4; ni++) {
            int cb = n0 + wn + ni * 8 + 2 * tq;
            float2 bia = *(const float2*)&bias[cb];
            float* c = acc[mi][ni];
            *(float2*)&g_xg[(size_t)r0 * G3 + cb] =
                make_float2(c[0] + bia.x, c[1] + bia.y);
            *(float2*)&g_xg[(size_t)(r0 + 8) * G3 + cb] =
                make_float2(c[2] + bia.x, c[3] + bia.y);
        }
    }
}

// ---------------------------------------------------------------------------
// fp32 SGEMM for layer-0 xg (K = 118). (unchanged, passing)
// ---------------------------------------------------------------------------
__global__ __launch_bounds__(256) void gemm_xg_kernel(
    const float* __restrict__ x_in, int K,
    const float* __restrict__ W, const float* __restrict__ bias)
{
    const float* A = x_in;

    __shared__ float As[8][128];
    __shared__ float Bs[8][128];

    const int n0 = blockIdx.x * 128;
    const int m0 = blockIdx.y * 128;
    const int tid = threadIdx.x;
    const int tx = tid & 15;
    const int ty = tid >> 4;

    float acc[8][8];
#pragma unroll
    for (int i = 0; i < 8; i++)
#pragma unroll
        for (int j = 0; j < 8; j++) acc[i][j] = 0.f;

    const int nkt = (K + 7) >> 3;
    for (int kt = 0; kt < nkt; kt++) {
        const int k0 = kt << 3;
#pragma unroll
        for (int i = 0; i < 4; i++) {
            int ii = tid + i * 256;
            int m = ii >> 3, k = ii & 7;
            As[k][m] = (k0 + k < K) ? A[(size_t)(m0 + m) * K + (k0 + k)] : 0.f;
        }
#pragma unroll
        for (int i = 0; i < 4; i++) {
            int ii = tid + i * 256;
            int n = ii >> 3, k = ii & 7;
            Bs[k][n] = (k0 + k < K) ? W[(size_t)(n0 + n) * K + (k0 + k)] : 0.f;
        }
        __syncthreads();
#pragma unroll
        for (int k = 0; k < 8; k++) {
            float a[8], b[8];
#pragma unroll
            for (int i = 0; i < 8; i++) a[i] = As[k][ty * 8 + i];
#pragma unroll
            for (int j = 0; j < 8; j++) b[j] = Bs[k][tx * 8 + j];
#pragma unroll
            for (int i = 0; i < 8; i++)
#pragma unroll
                for (int j = 0; j < 8; j++)
                    acc[i][j] = fmaf(a[i], b[j], acc[i][j]);
        }
        __syncthreads();
    }

#pragma unroll
    for (int i = 0; i < 8; i++) {
        size_t row = (size_t)(m0 + ty * 8 + i) * G3;
#pragma unroll
        for (int j = 0; j < 8; j++) {
            int n = n0 + tx * 8 + j;
            g_xg[row + n] = acc[i][j] + bias[n];
        }
    }
}

// ---------------------------------------------------------------------------
// Final linear: out[b] = dot(h_last[b,:], W_lin) + b_lin
// ---------------------------------------------------------------------------
__global__ __launch_bounds__(256) void final_kernel(
    const float* __restrict__ Wlin, const float* __restrict__ blin,
    float* __restrict__ out)
{
    const int b = blockIdx.x;
    const float* h = g_hb + b * HID;
    float s = 0.f;
    for (int k = threadIdx.x; k < HID; k += 256) s += h[k] * Wlin[k];
#pragma unroll
    for (int o = 16; o > 0; o >>= 1) s += __shfl_down_sync(0xffffffffu, s, o);
    __shared__ float red[8];
    if ((threadIdx.x & 31) == 0) red[threadIdx.x >> 5] = s;
    __syncthreads();
    if (threadIdx.x < 8) {
        s = red[threadIdx.x];
#pragma unroll
        for (int o = 4; o > 0; o >>= 1) s += __shfl_down_sync(0xffu, s, o);
        if (threadIdx.x == 0) out[b] = s + blin[0];
    }
}

// ---------------------------------------------------------------------------
extern "C" void kernel_launch(void* const* d_in, const int* in_sizes, int n_in,
                              void* d_out, int out_size)
{
    const float* x      = (const float*)d_in[0];
    const float* W_ih0  = (const float*)d_in[1];
    const float* W_ih12 = (const float*)d_in[2];
    const float* W_hh   = (const float*)d_in[3];
    const float* b_ih   = (const float*)d_in[4];
    const float* b_hh   = (const float*)d_in[5];
    const float* W_lin  = (const float*)d_in[6];
    const float* b_lin  = (const float*)d_in[7];
    float* out = (float*)d_out;

    cudaFuncSetAttribute(gru_layer_kernel,
                         cudaFuncAttributeMaxDynamicSharedMemorySize, GSM_BYTES);
    const int smem_xg = 2 * XST_F * sizeof(float);
    cudaFuncSetAttribute(gemm_xg_tf32_kernel,
                         cudaFuncAttributeMaxDynamicSharedMemorySize, smem_xg);

    for (int l = 0; l < 3; l++) {
        const int    ysel  = (l == 0) ? 1 : (l == 1 ? 2 : 0);
        const float* Whh_l = W_hh + (size_t)l * G3 * HID;
        const float* bih_l = b_ih + (size_t)l * G3;
        const float* bhh_l = b_hh + (size_t)l * G3;

        if (l == 0) {
            dim3 ggrid(G3 / 128, BT / 128);
            gemm_xg_kernel<<<ggrid, 256>>>(x, DIN0, W_ih0, bih_l);
        } else {
            const float* Wih = W_ih12 + (size_t)(l - 1) * G3 * HID;
            dim3 ggrid(G3 / 64, BT / 128);
            gemm_xg_tf32_kernel<<<ggrid, 128, smem_xg>>>(l, Wih, bih_l);
        }

        gru_layer_kernel<<<NBLK, GNT, GSM_BYTES>>>(Whh_l, bhh_l, ysel);
    }

    final_kernel<<<BATCH, 256>>>(W_lin, b_lin, out);
}